// round 7
// baseline (speedup 1.0000x reference)
#include <cuda_runtime.h>
#include <cstdint>

// FixedGaussianBlur: depthwise 21x21 Gaussian (sigma=3), reflect padding,
// x[32,3,512,512] f32 -> y[32,3,512,512] f32.
// Separable, fused. TW=64, TH=128.
// Horizontal: streaming packed f32x2 DIRECT FROM GMEM (no raw smem tile),
// results into h-tile smem [148][66]. Vertical: packed f32x2 over col pairs,
// 8-row groups, conflict-free. Exactly one __syncthreads().

#define IMG_W 512
#define IMG_H 512
#define PAD 10
#define KS 21
#define TW 64
#define TH 128
#define HROWS 148            // TH + 2*PAD
#define SH_W 66              // h-tile stride (floats)
#define NTHREADS 512
#define NIMG 96
#define NUNITS 592           // HROWS * 4 segments of 16 outputs
#define SMEM_BYTES (HROWS * SH_W * 4)   // 39072

#define W0  0.13303900f
#define W1  0.12584950f
#define W2  0.10652928f
#define W3  0.08069223f
#define W4  0.05469397f
#define W5  0.03317359f
#define W6  0.01800488f
#define W7  0.00874446f
#define W8  0.00380033f
#define W9  0.00147793f
#define W10 0.00051432f

__device__ __forceinline__ float tap(int j) {
    constexpr float w[KS] = {W10, W9, W8, W7, W6, W5, W4, W3, W2, W1, W0,
                             W1, W2, W3, W4, W5, W6, W7, W8, W9, W10};
    return w[j];
}

__device__ __forceinline__ int reflect_idx(int i, int n) {
    i = (i < 0) ? -i : i;
    i = (i >= n) ? (2 * n - 2 - i) : i;
    return i;
}

__device__ __forceinline__ uint64_t bcast2(float f) {
    uint32_t b = __float_as_uint(f);
    return ((uint64_t)b << 32) | (uint64_t)b;
}

__device__ __forceinline__ uint64_t pkf2(float lo, float hi) {
    uint64_t r;
    asm("mov.b64 %0, {%1, %2};" : "=l"(r) : "f"(lo), "f"(hi));
    return r;
}

__device__ __forceinline__ void ffma2(uint64_t& d, uint64_t a, uint64_t b, uint64_t c) {
    asm("fma.rn.f32x2 %0, %1, %2, %3;" : "=l"(d) : "l"(a), "l"(b), "l"(c));
}

// Streaming horizontal filter reading straight from a gmem row.
// Outputs 2*NP values starting at gmem x = wx0 + 10; window = wx0 .. wx0+2*NP+19.
// REF=true applies x-reflection per element (edge blocks only).
template <int NP, bool REF>
__device__ __forceinline__ void hconv_gmem(const float* __restrict__ row,
                                           int wx0, uint64_t acc[NP]) {
    #pragma unroll
    for (int p = 0; p < NP; ++p) acc[p] = 0;
    float eprev_y = 0.0f;
    #pragma unroll
    for (int k = 0; k < NP + 10; ++k) {
        float2 e;
        if (!REF) {
            e = __ldg(reinterpret_cast<const float2*>(row + wx0 + 2 * k));
        } else {
            e.x = __ldg(row + reflect_idx(wx0 + 2 * k, IMG_W));
            e.y = __ldg(row + reflect_idx(wx0 + 2 * k + 1, IMG_W));
        }
        uint64_t Ek = pkf2(e.x, e.y);
        #pragma unroll
        for (int p = 0; p < NP; ++p) {
            int m = k - p;                        // even tap j = 2m
            if (m >= 0 && m <= 10) ffma2(acc[p], Ek, bcast2(tap(2 * m)), acc[p]);
        }
        if (k > 0) {
            uint64_t Ok = pkf2(eprev_y, e.x);     // odd pair
            #pragma unroll
            for (int p = 0; p < NP; ++p) {
                int m = k - 1 - p;                // odd tap j = 2m+1
                if (m >= 0 && m <= 9) ffma2(acc[p], Ok, bcast2(tap(2 * m + 1)), acc[p]);
            }
        }
        eprev_y = e.y;
    }
}

__global__ __launch_bounds__(NTHREADS, 3)
void gauss_blur_fused(const float* __restrict__ in, float* __restrict__ out) {
    extern __shared__ __align__(16) float h[];   // [HROWS][SH_W], cols 0..63 used

    const int tid = threadIdx.x;
    const int x0 = blockIdx.x * TW;
    const int y0 = blockIdx.y * TH;
    const float* __restrict__ base = in + (size_t)blockIdx.z * (IMG_W * IMG_H);

    const bool x_edge = (x0 < PAD) || (x0 + TW + PAD > IMG_W);

    // ---- Horizontal pass: 592 units (row, 16-col segment), gmem -> smem ----
    {
        const int row = tid >> 2;
        const int oc0 = (tid & 3) << 4;
        const int gy = reflect_idx(y0 - PAD + row, IMG_H);
        const float* rp = base + (size_t)gy * IMG_W;
        uint64_t acc[8];
        if (x_edge) hconv_gmem<8, true >(rp, x0 + oc0 - PAD, acc);
        else        hconv_gmem<8, false>(rp, x0 + oc0 - PAD, acc);
        uint64_t* d = reinterpret_cast<uint64_t*>(&h[row * SH_W + oc0]);
        #pragma unroll
        for (int p = 0; p < 8; ++p) d[p] = acc[p];
    }
    if (tid < NUNITS - NTHREADS) {   // 80 tail units, rows 128..147
        const int u = tid + NTHREADS;
        const int row = u >> 2;
        const int oc0 = (u & 3) << 4;
        const int gy = reflect_idx(y0 - PAD + row, IMG_H);
        const float* rp = base + (size_t)gy * IMG_W;
        uint64_t acc[8];
        if (x_edge) hconv_gmem<8, true >(rp, x0 + oc0 - PAD, acc);
        else        hconv_gmem<8, false>(rp, x0 + oc0 - PAD, acc);
        uint64_t* d = reinterpret_cast<uint64_t*>(&h[row * SH_W + oc0]);
        #pragma unroll
        for (int p = 0; p < 8; ++p) d[p] = acc[p];
    }
    __syncthreads();

    // ---- Vertical pass: 32 col-pairs x 16 groups of 8 rows ----
    {
        const int cp = tid & 31;              // output cols 2cp, 2cp+1
        const int g = (tid >> 5) << 3;        // first output row: 0,8,...,120

        uint64_t acc[8];
        #pragma unroll
        for (int o = 0; o < 8; ++o) acc[o] = 0;

        const float* col = h + 2 * cp;
        #pragma unroll
        for (int t = 0; t < 28; ++t) {
            uint64_t v2 = *reinterpret_cast<const uint64_t*>(col + (g + t) * SH_W);
            #pragma unroll
            for (int o = 0; o < 8; ++o) {
                int j = t - o;
                if (j >= 0 && j < KS) ffma2(acc[o], v2, bcast2(tap(j)), acc[o]);
            }
        }

        char* dst = (char*)(out + (size_t)blockIdx.z * (IMG_W * IMG_H)
                                + (size_t)(y0 + g) * IMG_W + (x0 + 2 * cp));
        #pragma unroll
        for (int o = 0; o < 8; ++o)
            *reinterpret_cast<uint64_t*>(dst + (size_t)o * IMG_W * 4) = acc[o];
    }
}

extern "C" void kernel_launch(void* const* d_in, const int* in_sizes, int n_in,
                              void* d_out, int out_size) {
    (void)in_sizes; (void)n_in; (void)out_size;
    const float* x = (const float*)d_in[0];
    float* y = (float*)d_out;
    cudaFuncSetAttribute(gauss_blur_fused,
                         cudaFuncAttributeMaxDynamicSharedMemorySize, SMEM_BYTES);
    dim3 grid(IMG_W / TW, IMG_H / TH, NIMG);  // 8 x 4 x 96
    gauss_blur_fused<<<grid, NTHREADS, SMEM_BYTES>>>(x, y);
}

// round 8
// speedup vs baseline: 1.7294x; 1.7294x over previous
#include <cuda_runtime.h>
#include <cstdint>

// FixedGaussianBlur: depthwise 21x21 Gaussian (sigma=3), reflect padding,
// x[32,3,512,512] f32 -> y[32,3,512,512] f32.
// Separable, fused, in-place smem tile. TW=64, TH=128 -> 148x84 tile (49.7 KB).
// Horizontal: scalar FFMA-imm in place, CONFLICT-FREE mapping (row=tid&127,
// seg=tid>>7: LDS.128 octets span 8 rows -> distinct bank quads).
// Vertical: packed fma.rn.f32x2 over col pairs, 8-row groups, conflict-free.

#define IMG_W 512
#define IMG_H 512
#define PAD 10
#define KS 21
#define TW 64
#define TH 128
#define SROWS 148          // TH + 2*PAD
#define SCOLS 84           // TW + 2*PAD
#define NTHREADS 512
#define NIMG 96
#define NU64 (SROWS * SCOLS / 2)        // 6216
#define SMEM_BYTES (SROWS * SCOLS * 4)  // 49728

#define W0  0.13303900f
#define W1  0.12584950f
#define W2  0.10652928f
#define W3  0.08069223f
#define W4  0.05469397f
#define W5  0.03317359f
#define W6  0.01800488f
#define W7  0.00874446f
#define W8  0.00380033f
#define W9  0.00147793f
#define W10 0.00051432f

__device__ __forceinline__ float tap(int j) {
    constexpr float w[KS] = {W10, W9, W8, W7, W6, W5, W4, W3, W2, W1, W0,
                             W1, W2, W3, W4, W5, W6, W7, W8, W9, W10};
    return w[j];
}

__device__ __forceinline__ int reflect_idx(int i, int n) {
    i = (i < 0) ? -i : i;
    i = (i >= n) ? (2 * n - 2 - i) : i;
    return i;
}

__device__ __forceinline__ uint64_t bcast2(float f) {
    uint32_t b = __float_as_uint(f);
    return ((uint64_t)b << 32) | (uint64_t)b;
}

__device__ __forceinline__ void ffma2(uint64_t& d, uint64_t a, uint64_t b, uint64_t c) {
    asm("fma.rn.f32x2 %0, %1, %2, %3;" : "=l"(d) : "l"(a), "l"(b), "l"(c));
}

// 16-output horizontal filter on one row segment: reads s[row][seg..seg+35].
__device__ __forceinline__ void hfilter16(const float* srow, float o[16]) {
    float v[36];
    const float4* p = reinterpret_cast<const float4*>(srow);
    #pragma unroll
    for (int q = 0; q < 9; ++q) {
        float4 t = p[q];
        v[4 * q + 0] = t.x; v[4 * q + 1] = t.y;
        v[4 * q + 2] = t.z; v[4 * q + 3] = t.w;
    }
    #pragma unroll
    for (int c = 0; c < 16; ++c) {
        float acc = v[c] * tap(0);
        #pragma unroll
        for (int j = 1; j < KS; ++j) acc = fmaf(v[c + j], tap(j), acc);
        o[c] = acc;
    }
}

__global__ __launch_bounds__(NTHREADS, 3)
void gauss_blur_fused(const float* __restrict__ in, float* __restrict__ out) {
    extern __shared__ __align__(16) float s[];   // [SROWS][SCOLS] row-major

    const int tid = threadIdx.x;
    const int x0 = blockIdx.x * TW;
    const int y0 = blockIdx.y * TH;
    const float* __restrict__ base = in + (size_t)blockIdx.z * (IMG_W * IMG_H);

    // ---- Load 148x84 tile ----
    const bool x_int = (x0 >= PAD) && (x0 + TW + PAD <= IMG_W);
    if (x_int) {
        int idx = tid;
        #pragma unroll
        for (int it = 0; it < (NU64 + NTHREADS - 1) / NTHREADS; ++it) {
            if (idx < NU64) {
                int r = idx / (SCOLS / 2);
                int c2 = idx - r * (SCOLS / 2);
                int gy = reflect_idx(y0 - PAD + r, IMG_H);
                uint64_t v = __ldg((const uint64_t*)(base + (size_t)gy * IMG_W
                                                     + (x0 - PAD) + 2 * c2));
                *reinterpret_cast<uint64_t*>(&s[r * SCOLS + 2 * c2]) = v;
            }
            idx += NTHREADS;
        }
    } else {
        int idx = tid;
        #pragma unroll
        for (int it = 0; it < (SROWS * SCOLS + NTHREADS - 1) / NTHREADS; ++it) {
            if (idx < SROWS * SCOLS) {
                int r = idx / SCOLS;
                int c = idx - r * SCOLS;
                int gy = reflect_idx(y0 - PAD + r, IMG_H);
                int gx = reflect_idx(x0 - PAD + c, IMG_W);
                s[r * SCOLS + c] = __ldg(base + (size_t)gy * IMG_W + gx);
            }
            idx += NTHREADS;
        }
    }
    __syncthreads();

    // ---- Horizontal pass, in place, conflict-free mapping ----
    // P1: rows 0..127 (row = tid&127, seg = tid>>7 -> octet = 8 rows, one seg).
    // P2: rows 128..147, 80 units (row = 128 + tid%20, seg = tid/20).
    {
        const int row1 = tid & 127;
        const int seg1 = (tid >> 7) << 4;          // 0,16,32,48
        float o1[16];
        hfilter16(&s[row1 * SCOLS + seg1], o1);
        __syncthreads();   // all P1 reads of the raw tile complete
        {
            float4* q = reinterpret_cast<float4*>(&s[row1 * SCOLS + seg1]);
            #pragma unroll
            for (int k = 0; k < 4; ++k)
                q[k] = make_float4(o1[4 * k], o1[4 * k + 1], o1[4 * k + 2], o1[4 * k + 3]);
        }
        // P2 compute: rows 128..147 raw rows untouched by P1 stores (rows 0..127)
        const bool p2 = (tid < 80);
        const int row2 = 128 + (tid % 20);
        const int seg2 = (tid / 20) << 4;
        float o2[16];
        if (p2) hfilter16(&s[row2 * SCOLS + seg2], o2);
        __syncthreads();   // P2 reads done + P1 stores visible
        if (p2) {
            float4* q = reinterpret_cast<float4*>(&s[row2 * SCOLS + seg2]);
            #pragma unroll
            for (int k = 0; k < 4; ++k)
                q[k] = make_float4(o2[4 * k], o2[4 * k + 1], o2[4 * k + 2], o2[4 * k + 3]);
        }
    }
    __syncthreads();

    // ---- Vertical pass: 32 col-pairs x 16 groups of 8 rows ----
    {
        const int cp = tid & 31;            // cols 2cp, 2cp+1
        const int g = (tid >> 5) << 3;      // first output row: 0,8,...,120

        uint64_t acc[8];
        #pragma unroll
        for (int o = 0; o < 8; ++o) acc[o] = 0;

        const float* col = s + 2 * cp;
        #pragma unroll
        for (int t = 0; t < 28; ++t) {
            uint64_t v2 = *reinterpret_cast<const uint64_t*>(col + (g + t) * SCOLS);
            #pragma unroll
            for (int o = 0; o < 8; ++o) {
                int j = t - o;
                if (j >= 0 && j < KS) {
                    int wi = (j <= 10) ? j : (20 - j);
                    ffma2(acc[o], v2, bcast2(tap(wi)), acc[o]);
                }
            }
        }

        char* dst = (char*)(out + (size_t)blockIdx.z * (IMG_W * IMG_H)
                                + (size_t)(y0 + g) * IMG_W + (x0 + 2 * cp));
        #pragma unroll
        for (int o = 0; o < 8; ++o)
            *reinterpret_cast<uint64_t*>(dst + (size_t)o * IMG_W * 4) = acc[o];
    }
}

extern "C" void kernel_launch(void* const* d_in, const int* in_sizes, int n_in,
                              void* d_out, int out_size) {
    (void)in_sizes; (void)n_in; (void)out_size;
    const float* x = (const float*)d_in[0];
    float* y = (float*)d_out;
    cudaFuncSetAttribute(gauss_blur_fused,
                         cudaFuncAttributeMaxDynamicSharedMemorySize, SMEM_BYTES);
    dim3 grid(IMG_W / TW, IMG_H / TH, NIMG);  // 8 x 4 x 96
    gauss_blur_fused<<<grid, NTHREADS, SMEM_BYTES>>>(x, y);
}